// round 1
// baseline (speedup 1.0000x reference)
#include <cuda_runtime.h>

#define NB 256
#define NT 1024
#define NI 64
#define NH 25
#define NG 100   // 4*H
#define NO 64
#define NM (NB*NT)  // 262144 rows

// Scratch for precomputed input gates: [NM][NG] floats = ~105 MB (static device array, allowed)
static __device__ float g_gates[(size_t)NM * NG];

typedef unsigned long long ull;

__device__ __forceinline__ ull pack2(float a, float b){
    ull r; asm("mov.b64 %0,{%1,%2};" : "=l"(r) : "f"(a), "f"(b)); return r;
}
__device__ __forceinline__ float2 unpack2(ull v){
    float2 r; asm("mov.b64 {%0,%1},%2;" : "=f"(r.x), "=f"(r.y) : "l"(v)); return r;
}
__device__ __forceinline__ ull fma2(ull a, ull b, ull c){
    ull d; asm("fma.rn.f32x2 %0,%1,%2,%3;" : "=l"(d) : "l"(a), "l"(b), "l"(c)); return d;
}
__device__ __forceinline__ ull add2(ull a, ull b){
    ull d; asm("add.rn.f32x2 %0,%1,%2;" : "=l"(d) : "l"(a), "l"(b)); return d;
}
__device__ __forceinline__ float rcpf(float x){
    float r; asm("rcp.approx.f32 %0,%1;" : "=f"(r) : "f"(x)); return r;
}
__device__ __forceinline__ float sigf(float x){
    // 1/(1+e^-x); e^-x -> inf for very negative x gives rcp(inf)=0: safe.
    return rcpf(1.0f + __expf(-x));
}
__device__ __forceinline__ float tanh_f(float x){
    float ax = fabsf(x);
    float e  = __expf(-2.0f * ax);           // e in (0,1]: no inf path
    float t  = (1.0f - e) * rcpf(1.0f + e);
    return copysignf(t, x);
}

// ---------------------------------------------------------------------------
// Kernel 1: gates_x[row][j] = sum_i x[row][i]*W_ih[j][i] + (b_ih[j]+b_hh[j])
// M=262144, K=64, N=100. f32x2-packed column pairs, 250 threads,
// tile: 100 rows x 100 cols, K split in 2 passes of 32 (smem < 48KB).
// Thread = (pairc in 0..9, rowt in 0..24): 5 col-pairs x 4 rows = 20 FMA2/k.
// ---------------------------------------------------------------------------
__global__ void __launch_bounds__(256) gates_kernel(
    const float* __restrict__ x, const float* __restrict__ W_ih,
    const float* __restrict__ b_ih, const float* __restrict__ b_hh)
{
    __shared__ float xs[100][33];     // pad 33: rows land on distinct banks
    __shared__ ull   wps[32][50];     // wps[k][c] = (W_ih[2c][ks+k], W_ih[2c+1][ks+k])
    __shared__ float bsum[NG];

    const int tid   = threadIdx.x;          // 0..249
    const int pairc = tid % 10;
    const int rowt  = tid / 10;             // 0..24
    const int rowbase = blockIdx.x * 100;

    ull acc[4][5];
    #pragma unroll
    for (int r = 0; r < 4; r++)
        #pragma unroll
        for (int c = 0; c < 5; c++) acc[r][c] = 0ull;

    for (int pass = 0; pass < 2; pass++){
        const int ks = pass * 32;
        // stage x tile (100 rows x 32 k)
        for (int idx = tid; idx < 100*32; idx += 250){
            int r = idx >> 5, k = idx & 31;
            int grow = rowbase + r;
            xs[r][k] = (grow < NM) ? x[(size_t)grow * NI + ks + k] : 0.0f;
        }
        // stage packed W pairs (32 k x 50 pairs)
        for (int idx = tid; idx < 32*50; idx += 250){
            int k = idx / 50, c = idx % 50;
            wps[k][c] = pack2(W_ih[(2*c) * NI + ks + k], W_ih[(2*c+1) * NI + ks + k]);
        }
        if (pass == 0)
            for (int j = tid; j < NG; j += 250) bsum[j] = b_ih[j] + b_hh[j];
        __syncthreads();

        #pragma unroll 4
        for (int k = 0; k < 32; k++){
            ull xd[4], wv[5];
            #pragma unroll
            for (int r = 0; r < 4; r++){
                float v = xs[rowt + 25*r][k];
                xd[r] = pack2(v, v);
            }
            #pragma unroll
            for (int c = 0; c < 5; c++) wv[c] = wps[k][pairc + 10*c];
            #pragma unroll
            for (int r = 0; r < 4; r++)
                #pragma unroll
                for (int c = 0; c < 5; c++)
                    acc[r][c] = fma2(xd[r], wv[c], acc[r][c]);
        }
        __syncthreads();
    }

    #pragma unroll
    for (int r = 0; r < 4; r++){
        int grow = rowbase + rowt + 25*r;
        if (grow >= NM) continue;
        float* gp = g_gates + (size_t)grow * NG;
        #pragma unroll
        for (int c = 0; c < 5; c++){
            int j = 2 * (pairc + 10*c);
            float2 v = unpack2(acc[r][c]);
            v.x += bsum[j];
            v.y += bsum[j+1];
            *reinterpret_cast<float2*>(gp + j) = v;   // 8B aligned (j even, row*100 even)
        }
    }
}

// ---------------------------------------------------------------------------
// Kernel 2: sequential LSTM scan + fused FC head.
// 128 CTAs (<=148 SMs -> 1 CTA/SM), 192 threads = 2 batch lanes x 96 threads.
// Per lane: threads 0..49 = gate pairs, 64..95 = FC pairs, 0..24 = c/h update.
// Gate pairing keeps activation type uniform per half:
//   stid<25 : (i_s, f_s)  -> both sigmoid
//   stid>=25: (g_{s-25}, o_{s-25}) -> tanh on .x, sigmoid on .y
// h stored duplicated as f32x2 in smem: inner loop = 1 LDS.64 + 1 FMA2 per k.
// FC for h_{t-1} overlaps the gate phase of step t. Depth-4 gx prefetch ring.
// ---------------------------------------------------------------------------
__global__ void __launch_bounds__(192, 1) lstm_kernel(
    const float* __restrict__ W_hh, const float* __restrict__ W_fc,
    const float* __restrict__ b_fc, float* __restrict__ out)
{
    __shared__ ull   hd[2][NH];     // duplicated h per batch lane
    __shared__ float act[2][NG];    // activated gates per batch lane

    const int tid  = threadIdx.x;
    const int sub  = tid / 96;            // batch lane within CTA (warps 0-2 / 3-5)
    const int stid = tid - sub * 96;
    const int b    = blockIdx.x * 2 + sub;

    const float* gx = g_gates + (size_t)b * NT * NG;
    float*       ob = out     + (size_t)b * NT * NO;

    const bool is_gate = (stid < 50);
    const bool is_fc   = (stid >= 64);
    const int  o0      = 2 * (stid - 64);

    int j0 = 0, j1 = 0;
    ull wp[25];
    float c_reg = 0.0f;
    if (is_gate){
        if (stid < 25){ j0 = stid;      j1 = stid + 25; }   // (i, f)
        else          { j0 = stid + 25; j1 = stid + 50; }   // (g, o)
        #pragma unroll
        for (int k = 0; k < 25; k++)
            wp[k] = pack2(W_hh[j0 * NH + k], W_hh[j1 * NH + k]);
    }
    ull wf[25]; ull bfc = 0ull;
    if (is_fc){
        #pragma unroll
        for (int k = 0; k < 25; k++)
            wf[k] = pack2(W_fc[o0 * NH + k], W_fc[(o0+1) * NH + k]);
        bfc = pack2(b_fc[o0], b_fc[o0+1]);
    }
    if (stid < 25) hd[sub][stid] = 0ull;   // h0 = 0
    __syncthreads();

    // depth-4 register prefetch ring for gx
    float p0[4], p1[4];
    if (is_gate){
        #pragma unroll
        for (int d = 0; d < 4; d++){
            p0[d] = gx[d * NG + j0];
            p1[d] = gx[d * NG + j1];
        }
    }

    for (int tb = 0; tb < NT; tb += 4){
        #pragma unroll
        for (int u = 0; u < 4; u++){
            const int t = tb + u;
            if (is_gate){
                ull acc0 = pack2(p0[u], p1[u]);   // gx already holds b_ih+b_hh
                const int tn = t + 4;
                if (tn < NT){                      // refill ring slot
                    p0[u] = gx[tn * NG + j0];
                    p1[u] = gx[tn * NG + j1];
                }
                ull acc1 = 0ull;
                #pragma unroll
                for (int k = 0; k < 24; k += 2){
                    acc0 = fma2(hd[sub][k],   wp[k],   acc0);
                    acc1 = fma2(hd[sub][k+1], wp[k+1], acc1);
                }
                acc0 = fma2(hd[sub][24], wp[24], acc0);
                float2 g = unpack2(add2(acc0, acc1));
                float a0 = (stid < 25) ? sigf(g.x) : tanh_f(g.x);
                float a1 = sigf(g.y);
                act[sub][j0] = a0;
                act[sub][j1] = a1;
            }
            if (is_fc && t > 0){
                // out[t-1] = h_{t-1} @ W_fc^T + b_fc (overlaps gate phase)
                ull acc0 = bfc, acc1 = 0ull;
                #pragma unroll
                for (int k = 0; k < 24; k += 2){
                    acc0 = fma2(hd[sub][k],   wf[k],   acc0);
                    acc1 = fma2(hd[sub][k+1], wf[k+1], acc1);
                }
                acc0 = fma2(hd[sub][24], wf[24], acc0);
                *reinterpret_cast<float2*>(ob + (size_t)(t-1) * NO + o0) =
                    unpack2(add2(acc0, acc1));
            }
            __syncthreads();
            if (stid < 25){
                float iv = act[sub][stid];
                float fv = act[sub][stid + 25];
                float gv = act[sub][stid + 50];
                float ov = act[sub][stid + 75];
                c_reg = fv * c_reg + iv * gv;
                float h = ov * tanh_f(c_reg);
                hd[sub][stid] = pack2(h, h);
            }
            __syncthreads();
        }
    }
    // final FC for h_{T-1}
    if (is_fc){
        ull acc0 = bfc, acc1 = 0ull;
        #pragma unroll
        for (int k = 0; k < 24; k += 2){
            acc0 = fma2(hd[sub][k],   wf[k],   acc0);
            acc1 = fma2(hd[sub][k+1], wf[k+1], acc1);
        }
        acc0 = fma2(hd[sub][24], wf[24], acc0);
        *reinterpret_cast<float2*>(ob + (size_t)(NT-1) * NO + o0) =
            unpack2(add2(acc0, acc1));
    }
}

extern "C" void kernel_launch(void* const* d_in, const int* in_sizes, int n_in,
                              void* d_out, int out_size)
{
    (void)in_sizes; (void)n_in; (void)out_size;
    const float* x    = (const float*)d_in[0];
    const float* W_ih = (const float*)d_in[1];
    const float* W_hh = (const float*)d_in[2];
    const float* b_ih = (const float*)d_in[3];
    const float* b_hh = (const float*)d_in[4];
    const float* W_fc = (const float*)d_in[5];
    const float* b_fc = (const float*)d_in[6];
    float* out = (float*)d_out;

    gates_kernel<<<(NM + 99) / 100, 250>>>(x, W_ih, b_ih, b_hh);
    lstm_kernel<<<NB / 2, 192>>>(W_hh, W_fc, b_fc, out);
}

// round 2
// speedup vs baseline: 1.4806x; 1.4806x over previous
#include <cuda_runtime.h>

#define NB 256
#define NT 1024
#define NI 64
#define NH 25
#define NG 100   // 4*H
#define NO 64
#define NM (NB*NT)  // 262144 rows

// Precomputed input gates, layout [row][k][4] = (i_k, f_k, g_k, o_k): ~105 MB
static __device__ float g_gates[(size_t)NM * NG];

typedef unsigned long long ull;

__device__ __forceinline__ ull pack2(float a, float b){
    ull r; asm("mov.b64 %0,{%1,%2};" : "=l"(r) : "f"(a), "f"(b)); return r;
}
__device__ __forceinline__ float2 unpack2(ull v){
    float2 r; asm("mov.b64 {%0,%1},%2;" : "=f"(r.x), "=f"(r.y) : "l"(v)); return r;
}
__device__ __forceinline__ ull fma2(ull a, ull b, ull c){
    ull d; asm("fma.rn.f32x2 %0,%1,%2,%3;" : "=l"(d) : "l"(a), "l"(b), "l"(c)); return d;
}
__device__ __forceinline__ ull add2(ull a, ull b){
    ull d; asm("add.rn.f32x2 %0,%1,%2;" : "=l"(d) : "l"(a), "l"(b)); return d;
}
__device__ __forceinline__ float rcpf(float x){
    float r; asm("rcp.approx.f32 %0,%1;" : "=f"(r) : "f"(x)); return r;
}
__device__ __forceinline__ float sigf(float x){
    return rcpf(1.0f + __expf(-x));      // e^-x -> inf gives rcp(inf)=0: safe
}
__device__ __forceinline__ float tanh_f(float x){
    float ax = fabsf(x);
    float e  = __expf(-2.0f * ax);       // in (0,1]
    float t  = (1.0f - e) * rcpf(1.0f + e);
    return copysignf(t, x);
}

// ---------------------------------------------------------------------------
// Kernel 1: g_gates[row][k*4+{0,1,2,3}] = (i,f,g,o)_k pre-activations
//          = x[row] . W_ih[gate_row] + b_ih + b_hh
// M=262144, K=64 (2 passes of 32), 100x100 tile, 250 threads.
// Pair c (0..49): c<25 -> rows (c, 25+c) = (i_k,f_k), out slot 4c
//                 c>=25 -> rows (25+c, 50+c) = (g_k,o_k), out slot 4(c-25)+2
// x staged in smem PRE-DUPLICATED as f32x2: inner loop = 9 LDS.64 + 20 FMA2.
// ---------------------------------------------------------------------------
__global__ void __launch_bounds__(256) gates_kernel(
    const float* __restrict__ x, const float* __restrict__ W_ih,
    const float* __restrict__ b_ih, const float* __restrict__ b_hh)
{
    __shared__ ull   xsd[100][33];    // duplicated (v,v); pad 33 -> rows 2 banks apart
    __shared__ ull   wps[32][50];     // wps[k][c] = packed W pair for pair c
    __shared__ float bsum[NG];

    const int tid   = threadIdx.x;          // 0..249
    const int pairc = tid % 10;
    const int rowt  = tid / 10;             // 0..24
    const int rowbase = blockIdx.x * 100;

    ull acc[4][5];
    #pragma unroll
    for (int r = 0; r < 4; r++)
        #pragma unroll
        for (int c = 0; c < 5; c++) acc[r][c] = 0ull;

    for (int pass = 0; pass < 2; pass++){
        const int ks = pass * 32;
        for (int idx = tid; idx < 100*32; idx += 250){
            int r = idx >> 5, k = idx & 31;
            int grow = rowbase + r;
            float v = (grow < NM) ? x[(size_t)grow * NI + ks + k] : 0.0f;
            xsd[r][k] = pack2(v, v);
        }
        for (int idx = tid; idx < 32*50; idx += 250){
            int k = idx / 50, c = idx % 50;
            int r0 = (c < 25) ? c      : 25 + c;
            int r1 = (c < 25) ? 25 + c : 50 + c;
            wps[k][c] = pack2(W_ih[r0 * NI + ks + k], W_ih[r1 * NI + ks + k]);
        }
        if (pass == 0)
            for (int j = tid; j < NG; j += 250) bsum[j] = b_ih[j] + b_hh[j];
        __syncthreads();

        #pragma unroll
        for (int k = 0; k < 32; k++){
            ull xd[4], wv[5];
            #pragma unroll
            for (int r = 0; r < 4; r++) xd[r] = xsd[rowt + 25*r][k];
            #pragma unroll
            for (int c = 0; c < 5; c++) wv[c] = wps[k][pairc + 10*c];
            #pragma unroll
            for (int r = 0; r < 4; r++)
                #pragma unroll
                for (int c = 0; c < 5; c++)
                    acc[r][c] = fma2(xd[r], wv[c], acc[r][c]);
        }
        __syncthreads();
    }

    #pragma unroll
    for (int r = 0; r < 4; r++){
        int grow = rowbase + rowt + 25*r;
        if (grow >= NM) continue;
        float* gp = g_gates + (size_t)grow * NG;
        #pragma unroll
        for (int cc = 0; cc < 5; cc++){
            int c = pairc + 10*cc;
            int base, r0, r1;
            if (c < 25){ base = 4*c;          r0 = c;      r1 = 25 + c; }
            else       { base = 4*(c-25) + 2; r0 = 25 + c; r1 = 50 + c; }
            float2 v = unpack2(acc[r][cc]);
            v.x += bsum[r0];
            v.y += bsum[r1];
            *reinterpret_cast<float2*>(gp + base) = v;   // 8B aligned
        }
    }
}

// ---------------------------------------------------------------------------
// Kernel 2: barrier-free warp-private LSTM scan + fused FC.
// 1 warp = 1 batch lane. Lane k owns gate rows (i_k,f_k,g_k,o_k) and (c_k,h_k).
// h broadcast via 25 SHFL per step; zero smem, zero __syncthreads.
// Lanes 25..31 clone lane 24 (clamped k) -> fully uniform, branch-free body.
// FC (2 outputs per lane, all 32 lanes) rides the same shfl'd h_{t-1}.
// Weights held entirely in registers (~75 f32x2 pairs).
// grid = 128 blocks x 64 threads (2 warps/block -> SMSP 0,1 of each SM).
// ---------------------------------------------------------------------------
__global__ void __launch_bounds__(64, 1) lstm_kernel(
    const float* __restrict__ W_hh, const float* __restrict__ W_fc,
    const float* __restrict__ b_fc, float* __restrict__ out)
{
    const int lane = threadIdx.x & 31;
    const int b    = blockIdx.x * 2 + (threadIdx.x >> 5);
    const int k    = (lane < NH) ? lane : NH - 1;     // lanes 25..31 clone k=24
    const int o0   = 2 * lane;                         // FC output pair

    const float* gx = g_gates + (size_t)b * NT * NG + 4 * k;
    float*       ob = out     + (size_t)b * NT * NO + o0;

    // Weights in registers
    ull w_if[NH], w_go[NH], wf[NH];
    #pragma unroll
    for (int kk = 0; kk < NH; kk++){
        w_if[kk] = pack2(__ldg(W_hh + (     k) * NH + kk), __ldg(W_hh + (NH  + k) * NH + kk));
        w_go[kk] = pack2(__ldg(W_hh + (2*NH+k) * NH + kk), __ldg(W_hh + (3*NH+k) * NH + kk));
        wf[kk]   = pack2(__ldg(W_fc + o0 * NH + kk),       __ldg(W_fc + (o0+1) * NH + kk));
    }
    const ull bfc = pack2(__ldg(b_fc + o0), __ldg(b_fc + o0 + 1));

    float h = 0.0f, c = 0.0f;

    // depth-4 prefetch ring for gx rows
    float4 p[4];
    #pragma unroll
    for (int d = 0; d < 4; d++)
        p[d] = *reinterpret_cast<const float4*>(gx + d * NG);

    for (int tb = 0; tb < NT; tb += 4){
        #pragma unroll
        for (int u = 0; u < 4; u++){
            const int t = tb + u;
            // accumulators: (i,f) and (g,o) pre-acts init from gx, FC init from bias
            ull a_if0 = pack2(p[u].x, p[u].y), a_if1 = 0ull;
            ull a_go0 = pack2(p[u].z, p[u].w), a_go1 = 0ull;
            ull a_fc0 = bfc,                   a_fc1 = 0ull;
            // refill ring slot (t+4)
            if (t + 4 < NT)
                p[u] = *reinterpret_cast<const float4*>(gx + (size_t)(t + 4) * NG);

            #pragma unroll
            for (int kk = 0; kk < NH; kk++){
                float hv = __shfl_sync(0xffffffffu, h, kk);   // h_{t-1}[kk]
                ull hd = pack2(hv, hv);
                if (kk & 1){
                    a_if1 = fma2(hd, w_if[kk], a_if1);
                    a_go1 = fma2(hd, w_go[kk], a_go1);
                    a_fc1 = fma2(hd, wf[kk],   a_fc1);
                } else {
                    a_if0 = fma2(hd, w_if[kk], a_if0);
                    a_go0 = fma2(hd, w_go[kk], a_go0);
                    a_fc0 = fma2(hd, wf[kk],   a_fc0);
                }
            }
            // FC output for h_{t-1} -> out row t-1
            if (t > 0)
                *reinterpret_cast<float2*>(ob + (size_t)(t - 1) * NO) =
                    unpack2(add2(a_fc0, a_fc1));

            float2 gif = unpack2(add2(a_if0, a_if1));
            float2 ggo = unpack2(add2(a_go0, a_go1));
            float iv = sigf(gif.x);
            float fv = sigf(gif.y);
            float gv = tanh_f(ggo.x);
            float ov = sigf(ggo.y);
            c = fv * c + iv * gv;
            h = ov * tanh_f(c);
        }
    }
    // final FC for h_{T-1}
    {
        ull a0 = bfc, a1 = 0ull;
        #pragma unroll
        for (int kk = 0; kk < NH; kk++){
            float hv = __shfl_sync(0xffffffffu, h, kk);
            ull hd = pack2(hv, hv);
            if (kk & 1) a1 = fma2(hd, wf[kk], a1);
            else        a0 = fma2(hd, wf[kk], a0);
        }
        *reinterpret_cast<float2*>(ob + (size_t)(NT - 1) * NO) = unpack2(add2(a0, a1));
    }
}

extern "C" void kernel_launch(void* const* d_in, const int* in_sizes, int n_in,
                              void* d_out, int out_size)
{
    (void)in_sizes; (void)n_in; (void)out_size;
    const float* x    = (const float*)d_in[0];
    const float* W_ih = (const float*)d_in[1];
    const float* W_hh = (const float*)d_in[2];
    const float* b_ih = (const float*)d_in[3];
    const float* b_hh = (const float*)d_in[4];
    const float* W_fc = (const float*)d_in[5];
    const float* b_fc = (const float*)d_in[6];
    float* out = (float*)d_out;

    gates_kernel<<<(NM + 99) / 100, 250>>>(x, W_ih, b_ih, b_hh);
    lstm_kernel<<<NB / 2, 64>>>(W_hh, W_fc, b_fc, out);
}

// round 3
// speedup vs baseline: 1.5996x; 1.0803x over previous
#include <cuda_runtime.h>

#define NB 256
#define NT 1024
#define NI 64
#define NH 25
#define NG 100   // 4*H
#define NO 64
#define NM (NB*NT)  // 262144 rows

// Precomputed input gates, layout [row][k][4] = (i_k, f_k, g_k, o_k): ~105 MB
static __device__ float g_gates[(size_t)NM * NG];

typedef unsigned long long ull;

__device__ __forceinline__ ull pack2(float a, float b){
    ull r; asm("mov.b64 %0,{%1,%2};" : "=l"(r) : "f"(a), "f"(b)); return r;
}
__device__ __forceinline__ float2 unpack2(ull v){
    float2 r; asm("mov.b64 {%0,%1},%2;" : "=f"(r.x), "=f"(r.y) : "l"(v)); return r;
}
__device__ __forceinline__ ull fma2(ull a, ull b, ull c){
    ull d; asm("fma.rn.f32x2 %0,%1,%2,%3;" : "=l"(d) : "l"(a), "l"(b), "l"(c)); return d;
}
__device__ __forceinline__ ull add2(ull a, ull b){
    ull d; asm("add.rn.f32x2 %0,%1,%2;" : "=l"(d) : "l"(a), "l"(b)); return d;
}
// Single-MUFU tanh (sm_75+): lat ~16 cyc vs ~60 for the ex2/rcp sequence.
__device__ __forceinline__ float tanha(float x){
    float r; asm("tanh.approx.f32 %0,%1;" : "=f"(r) : "f"(x)); return r;
}
// sigmoid(x) = 0.5*tanh(0.5x) + 0.5  -> FMUL + MUFU + FMA
__device__ __forceinline__ float sig_t(float x){
    return fmaf(tanha(0.5f * x), 0.5f, 0.5f);
}

// ---------------------------------------------------------------------------
// Kernel 1: g_gates[row][k*4+{0,1,2,3}] = (i,f,g,o)_k pre-activations
//          = x[row] . W_ih[gate_row] + b_ih + b_hh     (unchanged from R2)
// ---------------------------------------------------------------------------
__global__ void __launch_bounds__(256) gates_kernel(
    const float* __restrict__ x, const float* __restrict__ W_ih,
    const float* __restrict__ b_ih, const float* __restrict__ b_hh)
{
    __shared__ ull   xsd[100][33];    // duplicated (v,v); pad 33
    __shared__ ull   wps[32][50];     // wps[k][c] = packed W pair for pair c
    __shared__ float bsum[NG];

    const int tid   = threadIdx.x;          // 0..249
    const int pairc = tid % 10;
    const int rowt  = tid / 10;             // 0..24
    const int rowbase = blockIdx.x * 100;

    ull acc[4][5];
    #pragma unroll
    for (int r = 0; r < 4; r++)
        #pragma unroll
        for (int c = 0; c < 5; c++) acc[r][c] = 0ull;

    for (int pass = 0; pass < 2; pass++){
        const int ks = pass * 32;
        for (int idx = tid; idx < 100*32; idx += 250){
            int r = idx >> 5, k = idx & 31;
            int grow = rowbase + r;
            float v = (grow < NM) ? x[(size_t)grow * NI + ks + k] : 0.0f;
            xsd[r][k] = pack2(v, v);
        }
        for (int idx = tid; idx < 32*50; idx += 250){
            int k = idx / 50, c = idx % 50;
            int r0 = (c < 25) ? c      : 25 + c;
            int r1 = (c < 25) ? 25 + c : 50 + c;
            wps[k][c] = pack2(W_ih[r0 * NI + ks + k], W_ih[r1 * NI + ks + k]);
        }
        if (pass == 0)
            for (int j = tid; j < NG; j += 250) bsum[j] = b_ih[j] + b_hh[j];
        __syncthreads();

        #pragma unroll
        for (int k = 0; k < 32; k++){
            ull xd[4], wv[5];
            #pragma unroll
            for (int r = 0; r < 4; r++) xd[r] = xsd[rowt + 25*r][k];
            #pragma unroll
            for (int c = 0; c < 5; c++) wv[c] = wps[k][pairc + 10*c];
            #pragma unroll
            for (int r = 0; r < 4; r++)
                #pragma unroll
                for (int c = 0; c < 5; c++)
                    acc[r][c] = fma2(xd[r], wv[c], acc[r][c]);
        }
        __syncthreads();
    }

    #pragma unroll
    for (int r = 0; r < 4; r++){
        int grow = rowbase + rowt + 25*r;
        if (grow >= NM) continue;
        float* gp = g_gates + (size_t)grow * NG;
        #pragma unroll
        for (int cc = 0; cc < 5; cc++){
            int c = pairc + 10*cc;
            int base, r0, r1;
            if (c < 25){ base = 4*c;          r0 = c;      r1 = 25 + c; }
            else       { base = 4*(c-25) + 2; r0 = 25 + c; r1 = 50 + c; }
            float2 v = unpack2(acc[r][cc]);
            v.x += bsum[r0];
            v.y += bsum[r1];
            *reinterpret_cast<float2*>(gp + base) = v;   // 8B aligned
        }
    }
}

// ---------------------------------------------------------------------------
// Kernel 2: barrier-free warp-private LSTM scan + fused FC.
// 1 warp = 1 batch lane; lane k owns (i,f,g,o)_k and (c_k,h_k); h broadcast
// via SHFL. Activations are single-MUFU tanh.approx (sigmoid via tanh).
// ---------------------------------------------------------------------------
__global__ void __launch_bounds__(64, 1) lstm_kernel(
    const float* __restrict__ W_hh, const float* __restrict__ W_fc,
    const float* __restrict__ b_fc, float* __restrict__ out)
{
    const int lane = threadIdx.x & 31;
    const int b    = blockIdx.x * 2 + (threadIdx.x >> 5);
    const int k    = (lane < NH) ? lane : NH - 1;     // lanes 25..31 clone k=24
    const int o0   = 2 * lane;                         // FC output pair

    const float* gx = g_gates + (size_t)b * NT * NG + 4 * k;
    float*       ob = out     + (size_t)b * NT * NO + o0;

    // Weights in registers
    ull w_if[NH], w_go[NH], wf[NH];
    #pragma unroll
    for (int kk = 0; kk < NH; kk++){
        w_if[kk] = pack2(__ldg(W_hh + (     k) * NH + kk), __ldg(W_hh + (NH  + k) * NH + kk));
        w_go[kk] = pack2(__ldg(W_hh + (2*NH+k) * NH + kk), __ldg(W_hh + (3*NH+k) * NH + kk));
        wf[kk]   = pack2(__ldg(W_fc + o0 * NH + kk),       __ldg(W_fc + (o0+1) * NH + kk));
    }
    const ull bfc = pack2(__ldg(b_fc + o0), __ldg(b_fc + o0 + 1));

    float h = 0.0f, c = 0.0f;

    // depth-4 prefetch ring for gx rows
    float4 p[4];
    #pragma unroll
    for (int d = 0; d < 4; d++)
        p[d] = *reinterpret_cast<const float4*>(gx + d * NG);

    for (int tb = 0; tb < NT; tb += 4){
        #pragma unroll
        for (int u = 0; u < 4; u++){
            const int t = tb + u;
            ull a_if0 = pack2(p[u].x, p[u].y), a_if1 = 0ull;
            ull a_go0 = pack2(p[u].z, p[u].w), a_go1 = 0ull;
            ull a_fc0 = bfc,                   a_fc1 = 0ull;
            if (t + 4 < NT)
                p[u] = *reinterpret_cast<const float4*>(gx + (size_t)(t + 4) * NG);

            #pragma unroll
            for (int kk = 0; kk < NH; kk++){
                float hv = __shfl_sync(0xffffffffu, h, kk);   // h_{t-1}[kk]
                ull hd = pack2(hv, hv);
                if (kk & 1){
                    a_if1 = fma2(hd, w_if[kk], a_if1);
                    a_go1 = fma2(hd, w_go[kk], a_go1);
                    a_fc1 = fma2(hd, wf[kk],   a_fc1);
                } else {
                    a_if0 = fma2(hd, w_if[kk], a_if0);
                    a_go0 = fma2(hd, w_go[kk], a_go0);
                    a_fc0 = fma2(hd, wf[kk],   a_fc0);
                }
            }
            // FC output for h_{t-1} -> out row t-1 (off the critical path)
            if (t > 0)
                *reinterpret_cast<float2*>(ob + (size_t)(t - 1) * NO) =
                    unpack2(add2(a_fc0, a_fc1));

            float2 gif = unpack2(add2(a_if0, a_if1));
            float2 ggo = unpack2(add2(a_go0, a_go1));
            float iv = sig_t(gif.x);
            float fv = sig_t(gif.y);
            float gv = tanha(ggo.x);
            float ov = sig_t(ggo.y);
            c = fv * c + iv * gv;
            h = ov * tanha(c);
        }
    }
    // final FC for h_{T-1}
    {
        ull a0 = bfc, a1 = 0ull;
        #pragma unroll
        for (int kk = 0; kk < NH; kk++){
            float hv = __shfl_sync(0xffffffffu, h, kk);
            ull hd = pack2(hv, hv);
            if (kk & 1) a1 = fma2(hd, wf[kk], a1);
            else        a0 = fma2(hd, wf[kk], a0);
        }
        *reinterpret_cast<float2*>(ob + (size_t)(NT - 1) * NO) = unpack2(add2(a0, a1));
    }
}

extern "C" void kernel_launch(void* const* d_in, const int* in_sizes, int n_in,
                              void* d_out, int out_size)
{
    (void)in_sizes; (void)n_in; (void)out_size;
    const float* x    = (const float*)d_in[0];
    const float* W_ih = (const float*)d_in[1];
    const float* W_hh = (const float*)d_in[2];
    const float* b_ih = (const float*)d_in[3];
    const float* b_hh = (const float*)d_in[4];
    const float* W_fc = (const float*)d_in[5];
    const float* b_fc = (const float*)d_in[6];
    float* out = (float*)d_out;

    gates_kernel<<<(NM + 99) / 100, 250>>>(x, W_ih, b_ih, b_hh);
    lstm_kernel<<<NB / 2, 64>>>(W_hh, W_fc, b_fc, out);
}